// round 14
// baseline (speedup 1.0000x reference)
#include <cuda_runtime.h>
#include <cuda_fp16.h>
#include <cuda_bf16.h>
#include <mma.h>
#include <cstdint>

using namespace nvcuda;

#define N_NODES 100000
#define N_EDGES 1600000
#define CH      128

// Scratch (static device globals — no allocation in kernel_launch)
__device__ __align__(16) __half g_h16[(size_t)N_NODES * CH];  // 25.6 MB fp16 h
__device__ int g_deg[N_NODES];
__device__ int g_any_hi;   // statically 0; reset by k_sniff_fin each replay
__device__ int g_is64;     // 1 if edge_index is int64
// W bf16 split images, row-major [o][k] (same layout as W)
__device__ __align__(16) __nv_bfloat16 g_Whi[CH * CH];
__device__ __align__(16) __nv_bfloat16 g_Wlo[CH * CH];

// ------------------- sniff dtype + init degree + W bf16 split (fused) -------
__global__ void k_sniff_deg(const int* __restrict__ w, const float* __restrict__ W) {
    int t = blockIdx.x * blockDim.x + threadIdx.x;      // 100096 threads
    if (t < N_NODES) g_deg[t] = 1;
    int i = (int)(((long long)t * 1599983LL) % 1600000LL);
    if (w[2 * i + 1] != 0) g_any_hi = 1;
    if (t < CH * CH) {
        float wv = W[t];
        __nv_bfloat16 hi = __float2bfloat16(wv);
        g_Whi[t] = hi;
        g_Wlo[t] = __float2bfloat16(wv - __bfloat162float(hi));
    }
}

__global__ void k_sniff_fin() {
    g_is64 = (g_any_hi == 0);
    g_any_hi = 0;                       // reset for next graph replay
}

__device__ __forceinline__ void edge_params(int* stride, int* dbase) {
    int f = g_is64;
    *stride = f ? 2 : 1;
    *dbase  = f ? 2 * N_EDGES : N_EDGES;
}

// ---------------------------------------------------------------- degree ----
__global__ void k_deg_count(const int* __restrict__ ei) {
    int e = blockIdx.x * blockDim.x + threadIdx.x;
    if (e >= N_EDGES) return;
    int stride, dbase; edge_params(&stride, &dbase);
    atomicAdd(&g_deg[ei[dbase + stride * e]], 1);
}

// ------------------------------------------- 2D-tiled wmma bf16 split GEMM --
// h[m][o] = b[o] + sum_k x[m][k] * W[o][k]
// 3-term split: xh*Wh + xl*Wh + xh*Wl (f32 acc), err ~2^-17.
// Block = 128 rows, 256 threads (8 warps as 2 row-groups x 4 col-groups).
// Warp (r,c) owns 4 row-tiles x 2 col-tiles -> per k-step: 8 A-frags +
// 4 B-frags, 24 MMAs. x(hi/lo) and W(hi/lo) staged in 128KB dynamic smem.
// Fused epilogue: out = h/deg (fp32 self term), g_h16 = fp16(h).
__device__ __forceinline__ unsigned int pack_bf2(__nv_bfloat16 a, __nv_bfloat16 b) {
    return (unsigned int)__bfloat16_as_ushort(a)
         | ((unsigned int)__bfloat16_as_ushort(b) << 16);
}

#define GEMM_SMEM (131072 + 512)

__global__ void __launch_bounds__(256, 1) k_gemm(const float* __restrict__ x,
                                                 const float* __restrict__ bias,
                                                 float* __restrict__ out) {
    extern __shared__ __align__(16) char sbuf[];
    __nv_bfloat16* xh = (__nv_bfloat16*)sbuf;               // [128][128] 32KB
    __nv_bfloat16* xl = (__nv_bfloat16*)(sbuf + 32768);     // [128][128] 32KB
    __nv_bfloat16* Wh = (__nv_bfloat16*)(sbuf + 65536);     // [128][128] 32KB
    __nv_bfloat16* Wl = (__nv_bfloat16*)(sbuf + 98304);     // [128][128] 32KB
    float*         sb = (float*)(sbuf + 131072);            // bias [128]
    float*         sa = (float*)sbuf;                       // f32 staging (reuse)

    const int t = threadIdx.x;
    const int w = t >> 5;
    const int wr = w >> 2;          // row group 0..1
    const int wc = w & 3;           // col group 0..3
    const size_t row0 = (size_t)blockIdx.x * 128;

    if (t < CH) sb[t] = bias[t];

    // Stage W hi/lo (uint4: 2048 each -> 8 per thread)
    {
        const uint4* swh = (const uint4*)g_Whi;
        const uint4* swl = (const uint4*)g_Wlo;
        uint4* dwh = (uint4*)Wh;
        uint4* dwl = (uint4*)Wl;
        #pragma unroll
        for (int i = 0; i < 8; i++) {
            int v = t + i * 256;
            dwh[v] = swh[v];
            dwl[v] = swl[v];
        }
    }

    // Stage x -> bf16 hi/lo (128 rows x 32 float4 = 4096 -> 16 per thread)
    #pragma unroll
    for (int i = 0; i < 16; i++) {
        int v = t + i * 256;
        int r = v >> 5, q = v & 31;
        float4 f = make_float4(0.f, 0.f, 0.f, 0.f);
        if (row0 + r < N_NODES) f = ((const float4*)x)[(row0 + r) * 32 + q];
        __nv_bfloat16 hx = __float2bfloat16(f.x), hy = __float2bfloat16(f.y);
        __nv_bfloat16 hz = __float2bfloat16(f.z), hw = __float2bfloat16(f.w);
        uint2 ph, pl;
        ph.x = pack_bf2(hx, hy);
        ph.y = pack_bf2(hz, hw);
        pl.x = pack_bf2(__float2bfloat16(f.x - __bfloat162float(hx)),
                        __float2bfloat16(f.y - __bfloat162float(hy)));
        pl.y = pack_bf2(__float2bfloat16(f.z - __bfloat162float(hz)),
                        __float2bfloat16(f.w - __bfloat162float(hw)));
        ((uint2*)xh)[v] = ph;
        ((uint2*)xl)[v] = pl;
    }
    __syncthreads();

    wmma::fragment<wmma::accumulator, 16, 16, 16, float> acc[4][2];
    #pragma unroll
    for (int i = 0; i < 4; i++)
        #pragma unroll
        for (int j = 0; j < 2; j++)
            wmma::fill_fragment(acc[i][j], 0.0f);

    #pragma unroll
    for (int k0 = 0; k0 < CH; k0 += 16) {
        wmma::fragment<wmma::matrix_a, 16, 16, 16, __nv_bfloat16, wmma::row_major> ah[4], al[4];
        wmma::fragment<wmma::matrix_b, 16, 16, 16, __nv_bfloat16, wmma::col_major> bh[2], bl[2];
        #pragma unroll
        for (int i = 0; i < 4; i++) {
            int rbase = (wr * 64 + i * 16) * CH;
            wmma::load_matrix_sync(ah[i], xh + rbase + k0, CH);
            wmma::load_matrix_sync(al[i], xl + rbase + k0, CH);
        }
        #pragma unroll
        for (int j = 0; j < 2; j++) {
            int cbase = ((wc * 2 + j) * 16) * CH;
            wmma::load_matrix_sync(bh[j], Wh + cbase + k0, CH);
            wmma::load_matrix_sync(bl[j], Wl + cbase + k0, CH);
        }
        #pragma unroll
        for (int i = 0; i < 4; i++)
            #pragma unroll
            for (int j = 0; j < 2; j++) {
                wmma::mma_sync(acc[i][j], ah[i], bh[j], acc[i][j]);
                wmma::mma_sync(acc[i][j], al[i], bh[j], acc[i][j]);
                wmma::mma_sync(acc[i][j], ah[i], bl[j], acc[i][j]);
            }
    }

    __syncthreads();   // x/W staging dead; reuse as f32 accumulator staging
    #pragma unroll
    for (int i = 0; i < 4; i++)
        #pragma unroll
        for (int j = 0; j < 2; j++)
            wmma::store_matrix_sync(sa + (wr * 64 + i * 16) * CH + (wc * 2 + j) * 16,
                                    acc[i][j], CH, wmma::mem_row_major);
    __syncthreads();

    // Epilogue: +bias; g_h16 = fp16(h); out = h/deg (exact fp32 self term)
    #pragma unroll
    for (int i = 0; i < 16; i++) {
        int v = t + i * 256;
        int r = v >> 5, q = v & 31;
        size_t row = row0 + r;
        if (row < N_NODES) {
            float4 hv = ((const float4*)sa)[v];
            float4 bb = ((const float4*)sb)[q];
            hv.x += bb.x; hv.y += bb.y; hv.z += bb.z; hv.w += bb.w;

            __half2 p0 = __floats2half2_rn(hv.x, hv.y);
            __half2 p1 = __floats2half2_rn(hv.z, hv.w);
            uint2 pk;
            pk.x = *(unsigned int*)&p0;
            pk.y = *(unsigned int*)&p1;
            ((uint2*)g_h16)[row * 32 + q] = pk;

            float invd = 1.0f / (float)g_deg[row];
            ((float4*)out)[row * 32 + q] =
                make_float4(hv.x * invd, hv.y * invd, hv.z * invd, hv.w * invd);
        }
    }
}

// ------------------------------------------------------------ edge scatter --
// One warp per edge: gather fp16 h[src], scale, vector red.add.v4 into out[dst].
__global__ void __launch_bounds__(256) k_edges(const int* __restrict__ ei,
                                               float* __restrict__ out) {
    int e    = (blockIdx.x << 3) + (threadIdx.x >> 5);
    int lane = threadIdx.x & 31;
    if (e >= N_EDGES) return;

    int stride, dbase; edge_params(&stride, &dbase);
    int s = ei[stride * e];
    int d = ei[dbase + stride * e];
    float nrm = rsqrtf((float)g_deg[s] * (float)g_deg[d]);

    uint2 pk = ((const uint2*)g_h16)[(size_t)s * 32 + lane];
    float2 f0 = __half22float2(*(const __half2*)&pk.x);
    float2 f1 = __half22float2(*(const __half2*)&pk.y);

    float* p = out + (size_t)d * CH + lane * 4;      // 16B aligned
    asm volatile("red.global.add.v4.f32 [%0], {%1, %2, %3, %4};"
                 :: "l"(p), "f"(f0.x * nrm), "f"(f0.y * nrm),
                    "f"(f1.x * nrm), "f"(f1.y * nrm)
                 : "memory");
}

// ------------------------------------------------------------------- glue ---
extern "C" void kernel_launch(void* const* d_in, const int* in_sizes, int n_in,
                              void* d_out, int out_size) {
    const float* x  = (const float*)d_in[0];
    const int*   ei = (const int*)d_in[1];     // int32 or int64 (sniffed)
    const float* W  = (const float*)d_in[2];
    const float* b  = (const float*)d_in[3];
    float* out = (float*)d_out;

    cudaFuncSetAttribute(k_gemm, cudaFuncAttributeMaxDynamicSharedMemorySize,
                         GEMM_SMEM);

    k_sniff_deg<<<(N_NODES + 255) / 256, 256>>>(ei, W);       // launch 0
    k_sniff_fin<<<1, 1>>>();                                  // launch 1
    k_deg_count<<<(N_EDGES + 255) / 256, 256>>>(ei);          // launch 2
    k_gemm<<<(N_NODES + 127) / 128, 256, GEMM_SMEM>>>(x, b, out);  // launch 3
    k_edges<<<N_EDGES / 8, 256>>>(ei, out);                   // launch 4
}

// round 15
// speedup vs baseline: 1.0972x; 1.0972x over previous
#include <cuda_runtime.h>
#include <cuda_fp16.h>
#include <cstdint>

#define N_NODES 100000
#define N_EDGES 1600000
#define CH      128

typedef unsigned long long ull;

// Scratch (static device globals — no allocation in kernel_launch)
__device__ __align__(16) __half g_h16[(size_t)N_NODES * CH];  // 25.6 MB fp16 h
__device__ int g_deg[N_NODES];
// Monotone dtype flag: statically 0; k_sniff_deg sets 1 iff any odd 32-bit
// word of the edge buffer is nonzero (=> int32 data). Value depends only on
// the input, is never reset, and is stable across graph replays.
__device__ int g_any_hi;

// --------------------------------------- sniff dtype + init degree (fused) --
__global__ void k_sniff_deg(const int* __restrict__ w) {
    int t = blockIdx.x * blockDim.x + threadIdx.x;      // 100096 threads
    if (t < N_NODES) g_deg[t] = 1;                      // self-loop
    int i = (int)(((long long)t * 1599983LL) % 1600000LL);
    if (w[2 * i + 1] != 0) g_any_hi = 1;
}

// any_hi != 0  => int32 layout (stride 1, dst at +N)
// any_hi == 0  => int64 layout (stride 2, dst at +2N, low words)
__device__ __forceinline__ void edge_params(int* stride, int* dbase) {
    int is32 = g_any_hi;
    *stride = is32 ? 1 : 2;
    *dbase  = is32 ? N_EDGES : 2 * N_EDGES;
}

// ---------------------------------------------------------------- degree ----
__global__ void k_deg_count(const int* __restrict__ ei) {
    int e = blockIdx.x * blockDim.x + threadIdx.x;
    if (e >= N_EDGES) return;
    int stride, dbase; edge_params(&stride, &dbase);
    atomicAdd(&g_deg[ei[dbase + stride * e]], 1);
}

// ------------------------------------------------------------------ GEMM ----
// (R10 exact — proven 109.5 us.) h = x W^T + b; fused epilogue:
// out = h/deg (exact fp32 self term), g_h16 = fp16(h).
// 128 threads, 4 warps, 32 rows/block (grid 3125). Microtile 8x4, FFMA2.
__global__ void __launch_bounds__(128) k_gemm(const float* __restrict__ x,
                                              const float* __restrict__ W,
                                              const float* __restrict__ bias,
                                              float* __restrict__ out) {
    __shared__ float xs[32][CH];
    __shared__ float wt[32][CH];   // wt[kk][o] = W[o][kc+kk]

    const int t    = threadIdx.x;
    const int w    = t >> 5;
    const int lane = t & 31;

    const float4* xg = (const float4*)(x + (size_t)blockIdx.x * 32 * CH);
    #pragma unroll
    for (int i = 0; i < 8; i++) {
        int v = t + i * 128;
        ((float4*)&xs[0][0])[v] = xg[v];
    }

    float4 b4 = ((const float4*)bias)[lane];
    ull acc[8][2];
    #pragma unroll
    for (int r = 0; r < 8; r++) {
        asm("mov.b64 %0, {%1, %2};" : "=l"(acc[r][0])
            : "r"(__float_as_uint(b4.x)), "r"(__float_as_uint(b4.y)));
        asm("mov.b64 %0, {%1, %2};" : "=l"(acc[r][1])
            : "r"(__float_as_uint(b4.z)), "r"(__float_as_uint(b4.w)));
    }

    for (int kc = 0; kc < CH; kc += 32) {
        __syncthreads();
        #pragma unroll
        for (int i = 0; i < 8; i++) {
            float4 f = *(const float4*)(W + (size_t)t * CH + kc + i * 4);
            wt[i * 4 + 0][t] = f.x;
            wt[i * 4 + 1][t] = f.y;
            wt[i * 4 + 2][t] = f.z;
            wt[i * 4 + 3][t] = f.w;
        }
        __syncthreads();

        #pragma unroll
        for (int g = 0; g < 8; g++) {
            const int k0 = g * 4;
            ulonglong2 bq0 = *(const ulonglong2*)&wt[k0 + 0][lane * 4];
            ulonglong2 bq1 = *(const ulonglong2*)&wt[k0 + 1][lane * 4];
            ulonglong2 bq2 = *(const ulonglong2*)&wt[k0 + 2][lane * 4];
            ulonglong2 bq3 = *(const ulonglong2*)&wt[k0 + 3][lane * 4];
            #pragma unroll
            for (int r = 0; r < 8; r++) {
                float4 a = *(const float4*)&xs[w * 8 + r][kc + k0];
                ull a0, a1, a2, a3;
                asm("mov.b64 %0, {%1, %1};" : "=l"(a0) : "r"(__float_as_uint(a.x)));
                asm("mov.b64 %0, {%1, %1};" : "=l"(a1) : "r"(__float_as_uint(a.y)));
                asm("mov.b64 %0, {%1, %1};" : "=l"(a2) : "r"(__float_as_uint(a.z)));
                asm("mov.b64 %0, {%1, %1};" : "=l"(a3) : "r"(__float_as_uint(a.w)));
                asm("fma.rn.f32x2 %0, %1, %2, %0;" : "+l"(acc[r][0]) : "l"(a0), "l"(bq0.x));
                asm("fma.rn.f32x2 %0, %1, %2, %0;" : "+l"(acc[r][1]) : "l"(a0), "l"(bq0.y));
                asm("fma.rn.f32x2 %0, %1, %2, %0;" : "+l"(acc[r][0]) : "l"(a1), "l"(bq1.x));
                asm("fma.rn.f32x2 %0, %1, %2, %0;" : "+l"(acc[r][1]) : "l"(a1), "l"(bq1.y));
                asm("fma.rn.f32x2 %0, %1, %2, %0;" : "+l"(acc[r][0]) : "l"(a2), "l"(bq2.x));
                asm("fma.rn.f32x2 %0, %1, %2, %0;" : "+l"(acc[r][1]) : "l"(a2), "l"(bq2.y));
                asm("fma.rn.f32x2 %0, %1, %2, %0;" : "+l"(acc[r][0]) : "l"(a3), "l"(bq3.x));
                asm("fma.rn.f32x2 %0, %1, %2, %0;" : "+l"(acc[r][1]) : "l"(a3), "l"(bq3.y));
            }
        }
    }

    #pragma unroll
    for (int r = 0; r < 8; r++) {
        unsigned int r0, r1, r2, r3;
        asm("mov.b64 {%0, %1}, %2;" : "=r"(r0), "=r"(r1) : "l"(acc[r][0]));
        asm("mov.b64 {%0, %1}, %2;" : "=r"(r2), "=r"(r3) : "l"(acc[r][1]));
        float4 hv = make_float4(__uint_as_float(r0), __uint_as_float(r1),
                                __uint_as_float(r2), __uint_as_float(r3));
        size_t row = (size_t)blockIdx.x * 32 + w * 8 + r;

        __half2 p0 = __floats2half2_rn(hv.x, hv.y);
        __half2 p1 = __floats2half2_rn(hv.z, hv.w);
        uint2 pk;
        pk.x = *(unsigned int*)&p0;
        pk.y = *(unsigned int*)&p1;
        ((uint2*)g_h16)[row * 32 + lane] = pk;

        float invd = 1.0f / (float)g_deg[row];
        ((float4*)out)[row * 32 + lane] =
            make_float4(hv.x * invd, hv.y * invd, hv.z * invd, hv.w * invd);
    }
}

// ------------------------------------------------------------ edge scatter --
// (R10 exact.) One warp per edge: gather fp16 h[src], scale by
// rsqrt(deg_s*deg_d), vector red.add.v4 into out[dst].
__global__ void __launch_bounds__(256) k_edges(const int* __restrict__ ei,
                                               float* __restrict__ out) {
    int e    = (blockIdx.x << 3) + (threadIdx.x >> 5);
    int lane = threadIdx.x & 31;
    if (e >= N_EDGES) return;

    int stride, dbase; edge_params(&stride, &dbase);
    int s = ei[stride * e];
    int d = ei[dbase + stride * e];
    float nrm = rsqrtf((float)g_deg[s] * (float)g_deg[d]);

    uint2 pk = ((const uint2*)g_h16)[(size_t)s * 32 + lane];
    float2 f0 = __half22float2(*(const __half2*)&pk.x);
    float2 f1 = __half22float2(*(const __half2*)&pk.y);

    float* p = out + (size_t)d * CH + lane * 4;      // 16B aligned
    asm volatile("red.global.add.v4.f32 [%0], {%1, %2, %3, %4};"
                 :: "l"(p), "f"(f0.x * nrm), "f"(f0.y * nrm),
                    "f"(f1.x * nrm), "f"(f1.y * nrm)
                 : "memory");
}

// ------------------------------------------------------------------- glue ---
extern "C" void kernel_launch(void* const* d_in, const int* in_sizes, int n_in,
                              void* d_out, int out_size) {
    const float* x  = (const float*)d_in[0];
    const int*   ei = (const int*)d_in[1];     // int32 or int64 (sniffed)
    const float* W  = (const float*)d_in[2];
    const float* b  = (const float*)d_in[3];
    float* out = (float*)d_out;

    k_sniff_deg<<<(N_NODES + 255) / 256, 256>>>(ei);   // launch 0
    k_deg_count<<<(N_EDGES + 255) / 256, 256>>>(ei);   // launch 1
    k_gemm<<<N_NODES / 32, 128>>>(x, W, b, out);       // launch 2
    k_edges<<<N_EDGES / 8, 256>>>(ei, out);            // launch 3 (profiled)
}

// round 16
// speedup vs baseline: 1.3021x; 1.1867x over previous
#include <cuda_runtime.h>
#include <cuda_fp16.h>
#include <cstdint>

#define N_NODES 100000
#define N_EDGES 1600000
#define CH      128

typedef unsigned long long ull;

// Scratch (static device globals — no allocation in kernel_launch)
__device__ __align__(16) __half g_h16[(size_t)N_NODES * CH];  // 25.6 MB fp16 h
__device__ int g_deg[N_NODES];
// Monotone dtype flag: statically 0; set to 1 iff any odd 32-bit word of the
// edge buffer is nonzero (=> int32 data). Input-determined, replay-stable.
__device__ int g_any_hi;

// --------------------------------------- sniff dtype + init degree (fused) --
__global__ void k_sniff_deg(const int* __restrict__ w) {
    int t = blockIdx.x * blockDim.x + threadIdx.x;      // 100096 threads
    if (t < N_NODES) g_deg[t] = 1;                      // self-loop
    int i = (int)(((long long)t * 1599983LL) % 1600000LL);
    if (w[2 * i + 1] != 0) g_any_hi = 1;
}

__device__ __forceinline__ void edge_params(int* stride, int* dbase) {
    int is32 = g_any_hi;
    *stride = is32 ? 1 : 2;
    *dbase  = is32 ? N_EDGES : 2 * N_EDGES;
}

// ---------------------------------------------------------------- degree ----
__global__ void k_deg_count(const int* __restrict__ ei) {
    int e = blockIdx.x * blockDim.x + threadIdx.x;
    if (e >= N_EDGES) return;
    int stride, dbase; edge_params(&stride, &dbase);
    atomicAdd(&g_deg[ei[dbase + stride * e]], 1);
}

// ------------------------------------------------------------------ GEMM ----
// (R10 exact — proven 109.5 us.) h = x W^T + b; fused epilogue:
// out = h/deg (exact fp32 self term), g_h16 = fp16(h).
__global__ void __launch_bounds__(128) k_gemm(const float* __restrict__ x,
                                              const float* __restrict__ W,
                                              const float* __restrict__ bias,
                                              float* __restrict__ out) {
    __shared__ float xs[32][CH];
    __shared__ float wt[32][CH];   // wt[kk][o] = W[o][kc+kk]

    const int t    = threadIdx.x;
    const int w    = t >> 5;
    const int lane = t & 31;

    const float4* xg = (const float4*)(x + (size_t)blockIdx.x * 32 * CH);
    #pragma unroll
    for (int i = 0; i < 8; i++) {
        int v = t + i * 128;
        ((float4*)&xs[0][0])[v] = xg[v];
    }

    float4 b4 = ((const float4*)bias)[lane];
    ull acc[8][2];
    #pragma unroll
    for (int r = 0; r < 8; r++) {
        asm("mov.b64 %0, {%1, %2};" : "=l"(acc[r][0])
            : "r"(__float_as_uint(b4.x)), "r"(__float_as_uint(b4.y)));
        asm("mov.b64 %0, {%1, %2};" : "=l"(acc[r][1])
            : "r"(__float_as_uint(b4.z)), "r"(__float_as_uint(b4.w)));
    }

    for (int kc = 0; kc < CH; kc += 32) {
        __syncthreads();
        #pragma unroll
        for (int i = 0; i < 8; i++) {
            float4 f = *(const float4*)(W + (size_t)t * CH + kc + i * 4);
            wt[i * 4 + 0][t] = f.x;
            wt[i * 4 + 1][t] = f.y;
            wt[i * 4 + 2][t] = f.z;
            wt[i * 4 + 3][t] = f.w;
        }
        __syncthreads();

        #pragma unroll
        for (int g = 0; g < 8; g++) {
            const int k0 = g * 4;
            ulonglong2 bq0 = *(const ulonglong2*)&wt[k0 + 0][lane * 4];
            ulonglong2 bq1 = *(const ulonglong2*)&wt[k0 + 1][lane * 4];
            ulonglong2 bq2 = *(const ulonglong2*)&wt[k0 + 2][lane * 4];
            ulonglong2 bq3 = *(const ulonglong2*)&wt[k0 + 3][lane * 4];
            #pragma unroll
            for (int r = 0; r < 8; r++) {
                float4 a = *(const float4*)&xs[w * 8 + r][kc + k0];
                ull a0, a1, a2, a3;
                asm("mov.b64 %0, {%1, %1};" : "=l"(a0) : "r"(__float_as_uint(a.x)));
                asm("mov.b64 %0, {%1, %1};" : "=l"(a1) : "r"(__float_as_uint(a.y)));
                asm("mov.b64 %0, {%1, %1};" : "=l"(a2) : "r"(__float_as_uint(a.z)));
                asm("mov.b64 %0, {%1, %1};" : "=l"(a3) : "r"(__float_as_uint(a.w)));
                asm("fma.rn.f32x2 %0, %1, %2, %0;" : "+l"(acc[r][0]) : "l"(a0), "l"(bq0.x));
                asm("fma.rn.f32x2 %0, %1, %2, %0;" : "+l"(acc[r][1]) : "l"(a0), "l"(bq0.y));
                asm("fma.rn.f32x2 %0, %1, %2, %0;" : "+l"(acc[r][0]) : "l"(a1), "l"(bq1.x));
                asm("fma.rn.f32x2 %0, %1, %2, %0;" : "+l"(acc[r][1]) : "l"(a1), "l"(bq1.y));
                asm("fma.rn.f32x2 %0, %1, %2, %0;" : "+l"(acc[r][0]) : "l"(a2), "l"(bq2.x));
                asm("fma.rn.f32x2 %0, %1, %2, %0;" : "+l"(acc[r][1]) : "l"(a2), "l"(bq2.y));
                asm("fma.rn.f32x2 %0, %1, %2, %0;" : "+l"(acc[r][0]) : "l"(a3), "l"(bq3.x));
                asm("fma.rn.f32x2 %0, %1, %2, %0;" : "+l"(acc[r][1]) : "l"(a3), "l"(bq3.y));
            }
        }
    }

    #pragma unroll
    for (int r = 0; r < 8; r++) {
        unsigned int r0, r1, r2, r3;
        asm("mov.b64 {%0, %1}, %2;" : "=r"(r0), "=r"(r1) : "l"(acc[r][0]));
        asm("mov.b64 {%0, %1}, %2;" : "=r"(r2), "=r"(r3) : "l"(acc[r][1]));
        float4 hv = make_float4(__uint_as_float(r0), __uint_as_float(r1),
                                __uint_as_float(r2), __uint_as_float(r3));
        size_t row = (size_t)blockIdx.x * 32 + w * 8 + r;

        __half2 p0 = __floats2half2_rn(hv.x, hv.y);
        __half2 p1 = __floats2half2_rn(hv.z, hv.w);
        uint2 pk;
        pk.x = *(unsigned int*)&p0;
        pk.y = *(unsigned int*)&p1;
        ((uint2*)g_h16)[row * 32 + lane] = pk;

        float invd = 1.0f / (float)g_deg[row];
        ((float4*)out)[row * 32 + lane] =
            make_float4(hv.x * invd, hv.y * invd, hv.z * invd, hv.w * invd);
    }
}

// ------------------------------------------------------------ edge scatter --
// 4 edges per warp, fully unrolled: 8 front-batched broadcast index loads,
// then 4 INDEPENDENT gather->scale->red.v4 chains (MLP=4 on the L2-latency
// critical path). 8 warps/block, grid = E/32 = 50000.
__global__ void __launch_bounds__(256) k_edges(const int* __restrict__ ei,
                                               float* __restrict__ out) {
    int warp = (blockIdx.x << 3) + (threadIdx.x >> 5);
    int lane = threadIdx.x & 31;
    int e0 = warp << 2;                 // 4 consecutive edges

    int stride, dbase; edge_params(&stride, &dbase);

    int s0 = ei[stride * (e0 + 0)];
    int s1 = ei[stride * (e0 + 1)];
    int s2 = ei[stride * (e0 + 2)];
    int s3 = ei[stride * (e0 + 3)];
    int d0 = ei[dbase + stride * (e0 + 0)];
    int d1 = ei[dbase + stride * (e0 + 1)];
    int d2 = ei[dbase + stride * (e0 + 2)];
    int d3 = ei[dbase + stride * (e0 + 3)];

    // independent gathers (MLP=4)
    uint2 p0 = ((const uint2*)g_h16)[(size_t)s0 * 32 + lane];
    uint2 p1 = ((const uint2*)g_h16)[(size_t)s1 * 32 + lane];
    uint2 p2 = ((const uint2*)g_h16)[(size_t)s2 * 32 + lane];
    uint2 p3 = ((const uint2*)g_h16)[(size_t)s3 * 32 + lane];

    // independent norm chains
    float n0 = rsqrtf((float)g_deg[s0] * (float)g_deg[d0]);
    float n1 = rsqrtf((float)g_deg[s1] * (float)g_deg[d1]);
    float n2 = rsqrtf((float)g_deg[s2] * (float)g_deg[d2]);
    float n3 = rsqrtf((float)g_deg[s3] * (float)g_deg[d3]);

    float2 a0 = __half22float2(*(const __half2*)&p0.x);
    float2 b0 = __half22float2(*(const __half2*)&p0.y);
    float2 a1 = __half22float2(*(const __half2*)&p1.x);
    float2 b1 = __half22float2(*(const __half2*)&p1.y);
    float2 a2 = __half22float2(*(const __half2*)&p2.x);
    float2 b2 = __half22float2(*(const __half2*)&p2.y);
    float2 a3 = __half22float2(*(const __half2*)&p3.x);
    float2 b3 = __half22float2(*(const __half2*)&p3.y);

    float* q0 = out + (size_t)d0 * CH + lane * 4;
    float* q1 = out + (size_t)d1 * CH + lane * 4;
    float* q2 = out + (size_t)d2 * CH + lane * 4;
    float* q3 = out + (size_t)d3 * CH + lane * 4;

    asm volatile("red.global.add.v4.f32 [%0], {%1, %2, %3, %4};"
                 :: "l"(q0), "f"(a0.x * n0), "f"(a0.y * n0),
                    "f"(b0.x * n0), "f"(b0.y * n0) : "memory");
    asm volatile("red.global.add.v4.f32 [%0], {%1, %2, %3, %4};"
                 :: "l"(q1), "f"(a1.x * n1), "f"(a1.y * n1),
                    "f"(b1.x * n1), "f"(b1.y * n1) : "memory");
    asm volatile("red.global.add.v4.f32 [%0], {%1, %2, %3, %4};"
                 :: "l"(q2), "f"(a2.x * n2), "f"(a2.y * n2),
                    "f"(b2.x * n2), "f"(b2.y * n2) : "memory");
    asm volatile("red.global.add.v4.f32 [%0], {%1, %2, %3, %4};"
                 :: "l"(q3), "f"(a3.x * n3), "f"(a3.y * n3),
                    "f"(b3.x * n3), "f"(b3.y * n3) : "memory");
}

// ------------------------------------------------------------------- glue ---
extern "C" void kernel_launch(void* const* d_in, const int* in_sizes, int n_in,
                              void* d_out, int out_size) {
    const float* x  = (const float*)d_in[0];
    const int*   ei = (const int*)d_in[1];     // int32 or int64 (sniffed)
    const float* W  = (const float*)d_in[2];
    const float* b  = (const float*)d_in[3];
    float* out = (float*)d_out;

    k_sniff_deg<<<(N_NODES + 255) / 256, 256>>>(ei);   // launch 0
    k_deg_count<<<(N_EDGES + 255) / 256, 256>>>(ei);   // launch 1
    k_gemm<<<N_NODES / 32, 128>>>(x, W, b, out);       // launch 2
    k_edges<<<N_EDGES / 32, 256>>>(ei, out);           // launch 3 (profiled)
}

// round 17
// speedup vs baseline: 1.3232x; 1.0162x over previous
#include <cuda_runtime.h>
#include <cuda_fp16.h>
#include <cstdint>

#define N_NODES 100000
#define N_EDGES 1600000
#define CH      128

typedef unsigned long long ull;

// Scratch (static device globals — no allocation in kernel_launch)
__device__ __align__(16) __half g_h16[(size_t)N_NODES * CH];  // 25.6 MB fp16 h
__device__ int g_deg[N_NODES];
// Monotone dtype flag: statically 0; set to 1 iff any odd 32-bit word of the
// edge buffer is nonzero (=> int32 data). Input-determined, replay-stable.
__device__ int g_any_hi;

// --------------------------------------- sniff dtype + init degree (fused) --
__global__ void k_sniff_deg(const int* __restrict__ w) {
    int t = blockIdx.x * blockDim.x + threadIdx.x;      // 100096 threads
    if (t < N_NODES) g_deg[t] = 1;                      // self-loop
    int i = (int)(((long long)t * 1599983LL) % 1600000LL);
    if (w[2 * i + 1] != 0) g_any_hi = 1;
}

__device__ __forceinline__ void edge_params(int* stride, int* dbase) {
    int is32 = g_any_hi;
    *stride = is32 ? 1 : 2;
    *dbase  = is32 ? N_EDGES : 2 * N_EDGES;
}

// ---------------------------------------------------------------- degree ----
__global__ void k_deg_count(const int* __restrict__ ei) {
    int e = blockIdx.x * blockDim.x + threadIdx.x;
    if (e >= N_EDGES) return;
    int stride, dbase; edge_params(&stride, &dbase);
    atomicAdd(&g_deg[ei[dbase + stride * e]], 1);
}

// ------------------------------------------------------------------ GEMM ----
// (R10 exact — proven 109.5 us.) h = x W^T + b; fused epilogue:
// out = h/deg (exact fp32 self term), g_h16 = fp16(h).
__global__ void __launch_bounds__(128) k_gemm(const float* __restrict__ x,
                                              const float* __restrict__ W,
                                              const float* __restrict__ bias,
                                              float* __restrict__ out) {
    __shared__ float xs[32][CH];
    __shared__ float wt[32][CH];   // wt[kk][o] = W[o][kc+kk]

    const int t    = threadIdx.x;
    const int w    = t >> 5;
    const int lane = t & 31;

    const float4* xg = (const float4*)(x + (size_t)blockIdx.x * 32 * CH);
    #pragma unroll
    for (int i = 0; i < 8; i++) {
        int v = t + i * 128;
        ((float4*)&xs[0][0])[v] = xg[v];
    }

    float4 b4 = ((const float4*)bias)[lane];
    ull acc[8][2];
    #pragma unroll
    for (int r = 0; r < 8; r++) {
        asm("mov.b64 %0, {%1, %2};" : "=l"(acc[r][0])
            : "r"(__float_as_uint(b4.x)), "r"(__float_as_uint(b4.y)));
        asm("mov.b64 %0, {%1, %2};" : "=l"(acc[r][1])
            : "r"(__float_as_uint(b4.z)), "r"(__float_as_uint(b4.w)));
    }

    for (int kc = 0; kc < CH; kc += 32) {
        __syncthreads();
        #pragma unroll
        for (int i = 0; i < 8; i++) {
            float4 f = *(const float4*)(W + (size_t)t * CH + kc + i * 4);
            wt[i * 4 + 0][t] = f.x;
            wt[i * 4 + 1][t] = f.y;
            wt[i * 4 + 2][t] = f.z;
            wt[i * 4 + 3][t] = f.w;
        }
        __syncthreads();

        #pragma unroll
        for (int g = 0; g < 8; g++) {
            const int k0 = g * 4;
            ulonglong2 bq0 = *(const ulonglong2*)&wt[k0 + 0][lane * 4];
            ulonglong2 bq1 = *(const ulonglong2*)&wt[k0 + 1][lane * 4];
            ulonglong2 bq2 = *(const ulonglong2*)&wt[k0 + 2][lane * 4];
            ulonglong2 bq3 = *(const ulonglong2*)&wt[k0 + 3][lane * 4];
            #pragma unroll
            for (int r = 0; r < 8; r++) {
                float4 a = *(const float4*)&xs[w * 8 + r][kc + k0];
                ull a0, a1, a2, a3;
                asm("mov.b64 %0, {%1, %1};" : "=l"(a0) : "r"(__float_as_uint(a.x)));
                asm("mov.b64 %0, {%1, %1};" : "=l"(a1) : "r"(__float_as_uint(a.y)));
                asm("mov.b64 %0, {%1, %1};" : "=l"(a2) : "r"(__float_as_uint(a.z)));
                asm("mov.b64 %0, {%1, %1};" : "=l"(a3) : "r"(__float_as_uint(a.w)));
                asm("fma.rn.f32x2 %0, %1, %2, %0;" : "+l"(acc[r][0]) : "l"(a0), "l"(bq0.x));
                asm("fma.rn.f32x2 %0, %1, %2, %0;" : "+l"(acc[r][1]) : "l"(a0), "l"(bq0.y));
                asm("fma.rn.f32x2 %0, %1, %2, %0;" : "+l"(acc[r][0]) : "l"(a1), "l"(bq1.x));
                asm("fma.rn.f32x2 %0, %1, %2, %0;" : "+l"(acc[r][1]) : "l"(a1), "l"(bq1.y));
                asm("fma.rn.f32x2 %0, %1, %2, %0;" : "+l"(acc[r][0]) : "l"(a2), "l"(bq2.x));
                asm("fma.rn.f32x2 %0, %1, %2, %0;" : "+l"(acc[r][1]) : "l"(a2), "l"(bq2.y));
                asm("fma.rn.f32x2 %0, %1, %2, %0;" : "+l"(acc[r][0]) : "l"(a3), "l"(bq3.x));
                asm("fma.rn.f32x2 %0, %1, %2, %0;" : "+l"(acc[r][1]) : "l"(a3), "l"(bq3.y));
            }
        }
    }

    #pragma unroll
    for (int r = 0; r < 8; r++) {
        unsigned int r0, r1, r2, r3;
        asm("mov.b64 {%0, %1}, %2;" : "=r"(r0), "=r"(r1) : "l"(acc[r][0]));
        asm("mov.b64 {%0, %1}, %2;" : "=r"(r2), "=r"(r3) : "l"(acc[r][1]));
        float4 hv = make_float4(__uint_as_float(r0), __uint_as_float(r1),
                                __uint_as_float(r2), __uint_as_float(r3));
        size_t row = (size_t)blockIdx.x * 32 + w * 8 + r;

        __half2 p0 = __floats2half2_rn(hv.x, hv.y);
        __half2 p1 = __floats2half2_rn(hv.z, hv.w);
        uint2 pk;
        pk.x = *(unsigned int*)&p0;
        pk.y = *(unsigned int*)&p1;
        ((uint2*)g_h16)[row * 32 + lane] = pk;

        float invd = 1.0f / (float)g_deg[row];
        ((float4*)out)[row * 32 + lane] =
            make_float4(hv.x * invd, hv.y * invd, hv.z * invd, hv.w * invd);
    }
}

// ------------------------------------------------------------ edge scatter --
// 8 edges per warp, fully unrolled: 16 front-batched broadcast index loads,
// then 8 INDEPENDENT gather->scale->red.v4 chains (MLP=8 on the L2-latency
// critical path). 8 warps/block, grid = E/64 = 25000.
__global__ void __launch_bounds__(256) k_edges(const int* __restrict__ ei,
                                               float* __restrict__ out) {
    int warp = (blockIdx.x << 3) + (threadIdx.x >> 5);
    int lane = threadIdx.x & 31;
    int e0 = warp << 3;                 // 8 consecutive edges

    int stride, dbase; edge_params(&stride, &dbase);

    int s[8], d[8];
    #pragma unroll
    for (int i = 0; i < 8; i++) s[i] = ei[stride * (e0 + i)];
    #pragma unroll
    for (int i = 0; i < 8; i++) d[i] = ei[dbase + stride * (e0 + i)];

    // independent gathers (MLP=8)
    uint2 p[8];
    #pragma unroll
    for (int i = 0; i < 8; i++)
        p[i] = ((const uint2*)g_h16)[(size_t)s[i] * 32 + lane];

    // independent norm chains
    float n[8];
    #pragma unroll
    for (int i = 0; i < 8; i++)
        n[i] = rsqrtf((float)g_deg[s[i]] * (float)g_deg[d[i]]);

    #pragma unroll
    for (int i = 0; i < 8; i++) {
        float2 a = __half22float2(*(const __half2*)&p[i].x);
        float2 b = __half22float2(*(const __half2*)&p[i].y);
        float* q = out + (size_t)d[i] * CH + lane * 4;
        asm volatile("red.global.add.v4.f32 [%0], {%1, %2, %3, %4};"
                     :: "l"(q), "f"(a.x * n[i]), "f"(a.y * n[i]),
                        "f"(b.x * n[i]), "f"(b.y * n[i]) : "memory");
    }
}

// ------------------------------------------------------------------- glue ---
extern "C" void kernel_launch(void* const* d_in, const int* in_sizes, int n_in,
                              void* d_out, int out_size) {
    const float* x  = (const float*)d_in[0];
    const int*   ei = (const int*)d_in[1];     // int32 or int64 (sniffed)
    const float* W  = (const float*)d_in[2];
    const float* b  = (const float*)d_in[3];
    float* out = (float*)d_out;

    k_sniff_deg<<<(N_NODES + 255) / 256, 256>>>(ei);   // launch 0
    k_deg_count<<<(N_EDGES + 255) / 256, 256>>>(ei);   // launch 1
    k_gemm<<<N_NODES / 32, 128>>>(x, W, b, out);       // launch 2
    k_edges<<<N_EDGES / 64, 256>>>(ei, out);           // launch 3 (profiled)
}